// round 13
// baseline (speedup 1.0000x reference)
#include <cuda_runtime.h>
#include <cuda_fp16.h>
#include <cstdint>

#define HW    512
#define NPIX  (HW * HW)          // 262144
#define NC    64
#define CAP   16                 // bucket capacity (max Poisson(1) over 262k keys ~ 10)
#define MAXS  44                 // list slots/pixel: pass1 [0,9), pass2 [9, 9+35)
#define P2OFF 9
#define ZOFF  (NPIX * 128)       // byte offset of the zero row in g_refT

#define TR_BLOCKS (NPIX / 128)   // 2048 transpose-role blocks
#define PC_BLOCKS (NPIX / 256)   // 1024 precompute-role blocks

// Scratch (__device__ globals; zero-initialized at load, row NPIX never written)
// INVARIANT: g_cnt is all-zero on entry to kernel_launch (vote re-zeroes it).
__device__ __half g_refT[(size_t)(NPIX + 1) * NC];  // +1 zero row for masked slots
__device__ int    g_cnt[NPIX];                      // bucket counts for inverse nnf_rs
__device__ int    g_bucket[CAP][NPIX];              // interleaved: [slot][key] -> ref pixel r
__device__ int    g_list[MAXS][NPIX];               // SLOT-MAJOR lists of BYTE offsets
__device__ int    g_counts[NPIX];                   // m1 | (n2 << 16)

// ---------------------------------------------------------------------------
// 1) Invert nnf_rs into buckets (g_cnt is zero by invariant).
// ---------------------------------------------------------------------------
__global__ __launch_bounds__(256) void build_buckets_kernel(const int* __restrict__ nnf_rs) {
    const int r = blockIdx.x * 256 + threadIdx.x;
    const int2 nn = __ldg(&((const int2*)nnf_rs)[r]);   // (sy, sx) in [0,512)
    const int key = nn.x * HW + nn.y;
    const int slot = atomicAdd(&g_cnt[key], 1);
    if (slot < CAP) g_bucket[slot][key] = r;
}

// ---------------------------------------------------------------------------
// 2) FUSED: transpose-role blocks [0, TR_BLOCKS) convert ref (C,H,W) fp32 ->
//    refT (pix, C) fp16; precompute-role blocks build slot-major gather lists.
//    The two roles are independent; precompute depends only on buckets.
// ---------------------------------------------------------------------------
__global__ __launch_bounds__(256) void setup_fused_kernel(const float* __restrict__ ref,
                                                          const int* __restrict__ nnf_sr) {
    const int tid = threadIdx.x;

    if (blockIdx.x < TR_BLOCKS) {
        // ---------------- transpose role ----------------
        __shared__ float tile[64][129];
        const int pixBase = blockIdx.x * 128;
        const int wc = tid >> 5;      // 0..7
        const int ln = tid & 31;

        #pragma unroll
        for (int it = 0; it < 8; it++) {
            const int c = wc + it * 8;
            const float4 v = __ldg((const float4*)(ref + (size_t)c * NPIX + pixBase + ln * 4));
            tile[c][ln * 4 + 0] = v.x; tile[c][ln * 4 + 1] = v.y;
            tile[c][ln * 4 + 2] = v.z; tile[c][ln * 4 + 3] = v.w;
        }
        __syncthreads();

        #pragma unroll
        for (int it = 0; it < 4; it++) {
            const int idx = tid + it * 256;
            const int px = idx >> 3;          // 0..127
            const int chunk = idx & 7;        // 8 halves per chunk
            const int c0 = chunk * 8;
            uint4 o;
            __half2 h;
            h = __float22half2_rn(make_float2(tile[c0 + 0][px], tile[c0 + 1][px]));
            o.x = *(unsigned*)&h;
            h = __float22half2_rn(make_float2(tile[c0 + 2][px], tile[c0 + 3][px]));
            o.y = *(unsigned*)&h;
            h = __float22half2_rn(make_float2(tile[c0 + 4][px], tile[c0 + 5][px]));
            o.z = *(unsigned*)&h;
            h = __float22half2_rn(make_float2(tile[c0 + 6][px], tile[c0 + 7][px]));
            o.w = *(unsigned*)&h;
            ((uint4*)(g_refT + (size_t)(pixBase + px) * NC))[chunk] = o;
        }
    } else {
        // ---------------- precompute role ----------------
        const int t = (blockIdx.x - TR_BLOCKS) * 256 + tid;
        const int ty = t >> 9;
        const int tx = t & (HW - 1);

        int m1 = 0;            // pass1 fill [0, m1), m1 <= 9
        int p2 = P2OFF;        // pass2 fill [9, p2)

        #pragma unroll
        for (int dy = -1; dy <= 1; dy++) {
            #pragma unroll
            for (int dx = -1; dx <= 1; dx++) {
                const int sy = ty - dy, sx = tx - dx;
                if ((unsigned)sy < HW && (unsigned)sx < HW) {
                    const int sidx = sy * HW + sx;

                    // pass 1: s -> nnf_sr[s]+d
                    const int2 nn = __ldg(&((const int2*)nnf_sr)[sidx]);
                    const int qy = nn.x + dy, qx = nn.y + dx;
                    if ((unsigned)qy < HW && (unsigned)qx < HW)
                        g_list[m1++][t] = (qy * HW + qx) << 7;   // coalesced store

                    // pass 2: bucket entries r with nnf_rs[r] = s, q = r+d
                    int n = g_cnt[sidx];
                    if (n > CAP) n = CAP;
                    for (int i = 0; i < n; i++) {
                        const int r = g_bucket[i][sidx];          // coalesced (interleaved)
                        const int q2y = (r >> 9) + dy, q2x = (r & (HW - 1)) + dx;
                        if (((unsigned)q2y < HW) & ((unsigned)q2x < HW) && p2 < MAXS)
                            g_list[p2++][t] = ((q2y * HW + q2x) << 7);
                    }
                }
            }
        }
        g_counts[t] = m1 | ((p2 - P2OFF) << 16);
    }
}

// ---------------------------------------------------------------------------
// 3) Vote: FOUR pixels per warp. Lane l serves pixel-group l>>3 with a 16-byte
//    LDG.128 (8 channels). Slots beyond the per-pixel count are SEL-masked to
//    the L1-resident zero row. Epilogue re-zeroes g_cnt (invariant for the
//    next replay).
// ---------------------------------------------------------------------------
__global__ __launch_bounds__(512) void vote_kernel(float* __restrict__ out) {
    __shared__ __align__(16) int s_list[MAXS * 64];   // [slot][px], 11 KB
    __shared__ float s_out[64][65];
    const int tid  = threadIdx.x;
    const int warp = tid >> 5;                    // 0..15
    const int lane = tid & 31;
    const int pixBase = blockIdx.x * 64;

    // Stage 44 slot-rows of 64 ints each (16 int4 per row), coalesced.
    #pragma unroll
    for (int i = tid; i < MAXS * 16; i += 512) {
        const int j = i >> 4;                     // slot row
        const int k = i & 15;                     // int4 within row
        ((int4*)s_list)[i] = __ldg(((const int4*)(&g_list[j][pixBase])) + k);
    }
    __syncthreads();

    const int group = lane >> 3;                  // 0..3 -> pixel within warp
    const int sub   = lane & 7;                   // 16-byte chunk within row
    const int px    = warp * 4 + group;           // 0..63
    const int t     = pixBase + px;

    const int packed = __ldg(&g_counts[t]);
    const int m1 = packed & 0xffff;
    const int n2 = packed >> 16;
    // warp max of n2 across the 4 groups
    int n2max = n2;
    n2max = max(n2max, __shfl_xor_sync(0xffffffffu, n2max, 8));
    n2max = max(n2max, __shfl_xor_sync(0xffffffffu, n2max, 16));

    // Invariant maintenance: g_cnt dead after setup; re-zero for next replay.
    if (tid < 64) g_cnt[pixBase + tid] = 0;

    const char* base = (const char*)g_refT + sub * 16;
    const int* col = s_list + px;                 // entry j at col[j * 64]

    unsigned long long a1[4] = {0ull, 0ull, 0ull, 0ull};
    unsigned long long a2[4] = {0ull, 0ull, 0ull, 0ull};

    #define ACC1(acc, u)                                                      \
    {                                                                         \
        const float2 v_ = __half22float2(*(const __half2*)&(u));              \
        unsigned long long pv_;                                               \
        asm("mov.b64 %0, {%1, %2};" : "=l"(pv_) : "f"(v_.x), "f"(v_.y));      \
        asm("add.rn.f32x2 %0, %0, %1;" : "+l"(acc) : "l"(pv_));               \
    }
    #define ACC8(acc, d) { ACC1(acc[0], (d).x); ACC1(acc[1], (d).y);          \
                           ACC1(acc[2], (d).z); ACC1(acc[3], (d).w); }

    // --- pass 1: fixed 9 slots, SEL-masked by m1, chunks of 3 ---
    #pragma unroll
    for (int jb = 0; jb < 9; jb += 3) {
        const int o0 = (jb     < m1) ? col[(jb    ) * 64] : (int)ZOFF;
        const int o1 = (jb + 1 < m1) ? col[(jb + 1) * 64] : (int)ZOFF;
        const int o2 = (jb + 2 < m1) ? col[(jb + 2) * 64] : (int)ZOFF;
        const uint4 d0 = __ldg((const uint4*)(base + o0));
        const uint4 d1 = __ldg((const uint4*)(base + o1));
        const uint4 d2 = __ldg((const uint4*)(base + o2));
        ACC8(a1, d0); ACC8(a1, d1); ACC8(a1, d2);
    }

    // --- pass 2: dynamic to warp-max, SEL-masked by n2, chunks of 2 ---
    for (int j = 0; j < n2max; j += 2) {
        const int o0 = (j     < n2) ? col[(P2OFF + j    ) * 64] : (int)ZOFF;
        const int o1 = (j + 1 < n2) ? col[(P2OFF + j + 1) * 64] : (int)ZOFF;
        const uint4 d0 = __ldg((const uint4*)(base + o0));
        const uint4 d1 = __ldg((const uint4*)(base + o1));
        ACC8(a2, d0); ACC8(a2, d1);
    }
    #undef ACC8
    #undef ACC1

    const float ws = 1.0f / (float)NPIX;
    const float wr = 2.0f / (float)NPIX;
    const float w  = ws * (float)m1 + wr * (float)n2;
    const float inv = (w == 0.f) ? 1.f : (1.f / w);

    #pragma unroll
    for (int k = 0; k < 4; k++) {
        float2 v1, v2;
        asm("mov.b64 {%0, %1}, %2;" : "=f"(v1.x), "=f"(v1.y) : "l"(a1[k]));
        asm("mov.b64 {%0, %1}, %2;" : "=f"(v2.x), "=f"(v2.y) : "l"(a2[k]));
        s_out[px][sub * 8 + 2 * k]     = (ws * v1.x + wr * v2.x) * inv;
        s_out[px][sub * 8 + 2 * k + 1] = (ws * v1.y + wr * v2.y) * inv;
    }
    __syncthreads();

    // Writeout: 64 px x 64 ch = 4096 floats, coalesced 64-float rows.
    #pragma unroll
    for (int i = tid; i < 4096; i += 512) {
        const int c = i >> 6;
        const int p = i & 63;
        out[(size_t)c * NPIX + pixBase + p] = s_out[p][c];
    }
}

// ---------------------------------------------------------------------------
extern "C" void kernel_launch(void* const* d_in, const int* in_sizes, int n_in,
                              void* d_out, int out_size) {
    const float* ref    = (const float*)d_in[0];
    const int*   nnf_sr = (const int*)d_in[1];
    const int*   nnf_rs = (const int*)d_in[2];
    float*       out    = (float*)d_out;

    build_buckets_kernel<<<NPIX / 256, 256>>>(nnf_rs);
    setup_fused_kernel<<<TR_BLOCKS + PC_BLOCKS, 256>>>(ref, nnf_sr);
    vote_kernel<<<NPIX / 64, 512>>>(out);
}

// round 14
// speedup vs baseline: 1.0646x; 1.0646x over previous
#include <cuda_runtime.h>
#include <cuda_fp16.h>
#include <cstdint>

#define HW    512
#define NPIX  (HW * HW)          // 262144
#define NC    64
#define CAP   16                 // bucket capacity (max Poisson(1) over 262k keys ~ 10)
#define MAXS  44                 // list slots/pixel: pass1 [0,9), pass2 [9, 9+35)
#define P2OFF 9
#define ZOFF  (NPIX * 128)       // byte offset of the zero row in g_refT

// Scratch (__device__ globals; zero-initialized at load, row NPIX never written)
// INVARIANT: g_cnt is all-zero on entry to kernel_launch (vote re-zeroes it).
__device__ __half g_refT[(size_t)(NPIX + 1) * NC];  // +1 zero row for masked slots
__device__ int    g_cnt[NPIX];                      // bucket counts for inverse nnf_rs
__device__ int    g_bucket[CAP][NPIX];              // interleaved: [slot][key] -> ref pixel r
__device__ int    g_list[MAXS][NPIX];               // SLOT-MAJOR lists of BYTE offsets
__device__ int    g_counts[NPIX];                   // m1 | (n2 << 16)

// ---------------------------------------------------------------------------
// 1) Transpose + downconvert: ref (C,H,W) fp32 -> refT (H*W, C) fp16.
//    float4 loads, uint4 (8-half) stores, 128-px tiles.
// ---------------------------------------------------------------------------
__global__ __launch_bounds__(256) void transpose_ref_kernel(const float* __restrict__ ref) {
    __shared__ float tile[64][129];
    const int pixBase = blockIdx.x * 128;
    const int tid = threadIdx.x;
    const int wc = tid >> 5;      // 0..7
    const int ln = tid & 31;

    #pragma unroll
    for (int it = 0; it < 8; it++) {
        const int c = wc + it * 8;
        const float4 v = __ldg((const float4*)(ref + (size_t)c * NPIX + pixBase + ln * 4));
        tile[c][ln * 4 + 0] = v.x; tile[c][ln * 4 + 1] = v.y;
        tile[c][ln * 4 + 2] = v.z; tile[c][ln * 4 + 3] = v.w;
    }
    __syncthreads();

    #pragma unroll
    for (int it = 0; it < 4; it++) {
        const int idx = tid + it * 256;
        const int px = idx >> 3;          // 0..127
        const int chunk = idx & 7;        // 8 halves per chunk
        const int c0 = chunk * 8;
        uint4 o;
        __half2 h;
        h = __float22half2_rn(make_float2(tile[c0 + 0][px], tile[c0 + 1][px]));
        o.x = *(unsigned*)&h;
        h = __float22half2_rn(make_float2(tile[c0 + 2][px], tile[c0 + 3][px]));
        o.y = *(unsigned*)&h;
        h = __float22half2_rn(make_float2(tile[c0 + 4][px], tile[c0 + 5][px]));
        o.z = *(unsigned*)&h;
        h = __float22half2_rn(make_float2(tile[c0 + 6][px], tile[c0 + 7][px]));
        o.w = *(unsigned*)&h;
        ((uint4*)(g_refT + (size_t)(pixBase + px) * NC))[chunk] = o;
    }
}

// ---------------------------------------------------------------------------
// 2) Invert nnf_rs into buckets. FOUR pixels per thread: 4 independent
//    atomic chains in flight (ATOMG lat ~318 cyc was the old bottleneck).
//    g_cnt is all-zero on entry (invariant).
// ---------------------------------------------------------------------------
__global__ __launch_bounds__(256) void build_buckets_kernel(const int* __restrict__ nnf_rs) {
    const int base = blockIdx.x * 1024 + threadIdx.x;

    int2 nn[4];
    #pragma unroll
    for (int k = 0; k < 4; k++)
        nn[k] = __ldg(&((const int2*)nnf_rs)[base + k * 256]);

    #pragma unroll
    for (int k = 0; k < 4; k++) {
        const int key = nn[k].x * HW + nn[k].y;
        const int slot = atomicAdd(&g_cnt[key], 1);
        if (slot < CAP) g_bucket[slot][key] = base + k * 256;
    }
}

// ---------------------------------------------------------------------------
// 3) Precompute lists: one thread per pixel, NO smem. Slot-major g_list makes
//    every list store coalesced. Pass1 -> slots [0,m1), pass2 -> [9, 9+n2).
// ---------------------------------------------------------------------------
__global__ __launch_bounds__(256) void precompute_kernel(const int* __restrict__ nnf_sr) {
    const int t = blockIdx.x * 256 + threadIdx.x;
    const int ty = t >> 9;
    const int tx = t & (HW - 1);

    int m1 = 0;            // pass1 fill [0, m1), m1 <= 9
    int p2 = P2OFF;        // pass2 fill [9, p2)

    #pragma unroll
    for (int dy = -1; dy <= 1; dy++) {
        #pragma unroll
        for (int dx = -1; dx <= 1; dx++) {
            const int sy = ty - dy, sx = tx - dx;
            if ((unsigned)sy < HW && (unsigned)sx < HW) {
                const int sidx = sy * HW + sx;

                // pass 1: s -> nnf_sr[s]+d
                const int2 nn = __ldg(&((const int2*)nnf_sr)[sidx]);
                const int qy = nn.x + dy, qx = nn.y + dx;
                if ((unsigned)qy < HW && (unsigned)qx < HW)
                    g_list[m1++][t] = (qy * HW + qx) << 7;   // coalesced store

                // pass 2: bucket entries r with nnf_rs[r] = s, q = r+d
                int n = g_cnt[sidx];
                if (n > CAP) n = CAP;
                for (int i = 0; i < n; i++) {
                    const int r = g_bucket[i][sidx];          // coalesced (interleaved)
                    const int q2y = (r >> 9) + dy, q2x = (r & (HW - 1)) + dx;
                    if (((unsigned)q2y < HW) & ((unsigned)q2x < HW) && p2 < MAXS)
                        g_list[p2++][t] = ((q2y * HW + q2x) << 7);
                }
            }
        }
    }
    g_counts[t] = m1 | ((p2 - P2OFF) << 16);
}

// ---------------------------------------------------------------------------
// 4) Vote: FOUR pixels per warp. Lane l serves pixel-group l>>3 with a 16-byte
//    LDG.128 (8 channels). Slots beyond the per-pixel count are SEL-masked to
//    the L1-resident zero row. Epilogue re-zeroes g_cnt (invariant).
// ---------------------------------------------------------------------------
__global__ __launch_bounds__(512) void vote_kernel(float* __restrict__ out) {
    __shared__ __align__(16) int s_list[MAXS * 64];   // [slot][px], 11 KB
    __shared__ float s_out[64][65];
    const int tid  = threadIdx.x;
    const int warp = tid >> 5;                    // 0..15
    const int lane = tid & 31;
    const int pixBase = blockIdx.x * 64;

    // Stage 44 slot-rows of 64 ints each (16 int4 per row), coalesced.
    #pragma unroll
    for (int i = tid; i < MAXS * 16; i += 512) {
        const int j = i >> 4;                     // slot row
        const int k = i & 15;                     // int4 within row
        ((int4*)s_list)[i] = __ldg(((const int4*)(&g_list[j][pixBase])) + k);
    }
    __syncthreads();

    const int group = lane >> 3;                  // 0..3 -> pixel within warp
    const int sub   = lane & 7;                   // 16-byte chunk within row
    const int px    = warp * 4 + group;           // 0..63
    const int t     = pixBase + px;

    const int packed = __ldg(&g_counts[t]);
    const int m1 = packed & 0xffff;
    const int n2 = packed >> 16;
    // warp max of n2 across the 4 groups
    int n2max = n2;
    n2max = max(n2max, __shfl_xor_sync(0xffffffffu, n2max, 8));
    n2max = max(n2max, __shfl_xor_sync(0xffffffffu, n2max, 16));

    // Invariant maintenance: g_cnt dead after setup; re-zero for next replay.
    if (tid < 64) g_cnt[pixBase + tid] = 0;

    const char* base = (const char*)g_refT + sub * 16;
    const int* col = s_list + px;                 // entry j at col[j * 64]

    unsigned long long a1[4] = {0ull, 0ull, 0ull, 0ull};
    unsigned long long a2[4] = {0ull, 0ull, 0ull, 0ull};

    #define ACC1(acc, u)                                                      \
    {                                                                         \
        const float2 v_ = __half22float2(*(const __half2*)&(u));              \
        unsigned long long pv_;                                               \
        asm("mov.b64 %0, {%1, %2};" : "=l"(pv_) : "f"(v_.x), "f"(v_.y));      \
        asm("add.rn.f32x2 %0, %0, %1;" : "+l"(acc) : "l"(pv_));               \
    }
    #define ACC8(acc, d) { ACC1(acc[0], (d).x); ACC1(acc[1], (d).y);          \
                           ACC1(acc[2], (d).z); ACC1(acc[3], (d).w); }

    // --- pass 1: fixed 9 slots, SEL-masked by m1, chunks of 3 ---
    #pragma unroll
    for (int jb = 0; jb < 9; jb += 3) {
        const int o0 = (jb     < m1) ? col[(jb    ) * 64] : (int)ZOFF;
        const int o1 = (jb + 1 < m1) ? col[(jb + 1) * 64] : (int)ZOFF;
        const int o2 = (jb + 2 < m1) ? col[(jb + 2) * 64] : (int)ZOFF;
        const uint4 d0 = __ldg((const uint4*)(base + o0));
        const uint4 d1 = __ldg((const uint4*)(base + o1));
        const uint4 d2 = __ldg((const uint4*)(base + o2));
        ACC8(a1, d0); ACC8(a1, d1); ACC8(a1, d2);
    }

    // --- pass 2: dynamic to warp-max, SEL-masked by n2, chunks of 2 ---
    for (int j = 0; j < n2max; j += 2) {
        const int o0 = (j     < n2) ? col[(P2OFF + j    ) * 64] : (int)ZOFF;
        const int o1 = (j + 1 < n2) ? col[(P2OFF + j + 1) * 64] : (int)ZOFF;
        const uint4 d0 = __ldg((const uint4*)(base + o0));
        const uint4 d1 = __ldg((const uint4*)(base + o1));
        ACC8(a2, d0); ACC8(a2, d1);
    }
    #undef ACC8
    #undef ACC1

    const float ws = 1.0f / (float)NPIX;
    const float wr = 2.0f / (float)NPIX;
    const float w  = ws * (float)m1 + wr * (float)n2;
    const float inv = (w == 0.f) ? 1.f : (1.f / w);

    #pragma unroll
    for (int k = 0; k < 4; k++) {
        float2 v1, v2;
        asm("mov.b64 {%0, %1}, %2;" : "=f"(v1.x), "=f"(v1.y) : "l"(a1[k]));
        asm("mov.b64 {%0, %1}, %2;" : "=f"(v2.x), "=f"(v2.y) : "l"(a2[k]));
        s_out[px][sub * 8 + 2 * k]     = (ws * v1.x + wr * v2.x) * inv;
        s_out[px][sub * 8 + 2 * k + 1] = (ws * v1.y + wr * v2.y) * inv;
    }
    __syncthreads();

    // Writeout: 64 px x 64 ch = 4096 floats, coalesced 64-float rows.
    #pragma unroll
    for (int i = tid; i < 4096; i += 512) {
        const int c = i >> 6;
        const int p = i & 63;
        out[(size_t)c * NPIX + pixBase + p] = s_out[p][c];
    }
}

// ---------------------------------------------------------------------------
extern "C" void kernel_launch(void* const* d_in, const int* in_sizes, int n_in,
                              void* d_out, int out_size) {
    const float* ref    = (const float*)d_in[0];
    const int*   nnf_sr = (const int*)d_in[1];
    const int*   nnf_rs = (const int*)d_in[2];
    float*       out    = (float*)d_out;

    transpose_ref_kernel<<<NPIX / 128, 256>>>(ref);
    build_buckets_kernel<<<NPIX / 1024, 256>>>(nnf_rs);
    precompute_kernel<<<NPIX / 256, 256>>>(nnf_sr);
    vote_kernel<<<NPIX / 64, 512>>>(out);
}

// round 15
// speedup vs baseline: 1.1829x; 1.1111x over previous
#include <cuda_runtime.h>
#include <cuda_fp16.h>
#include <cstdint>

#define HW    512
#define NPIX  (HW * HW)          // 262144
#define NC    64
#define CAP   16                 // bucket capacity (max Poisson(1) over 262k keys ~ 10)
#define MAXS  44                 // list slots/pixel: pass1 [0,9), pass2 [9, 9+35)
#define P2OFF 9
#define ZOFF  (NPIX * 128)       // byte offset of the zero row in g_refT

// Scratch (__device__ globals; zero-initialized at load, row NPIX never written)
// INVARIANT: g_cnt is all-zero on entry to kernel_launch (vote re-zeroes it).
__device__ __half g_refT[(size_t)(NPIX + 1) * NC];  // +1 zero row for masked slots
__device__ int    g_cnt[NPIX];                      // bucket counts for inverse nnf_rs
__device__ int    g_bucket[CAP][NPIX];              // interleaved: [slot][key] -> ref pixel r
__device__ int    g_list[MAXS][NPIX];               // SLOT-MAJOR lists of BYTE offsets
__device__ int    g_counts[NPIX];                   // m1 | (n2 << 16)

// ---------------------------------------------------------------------------
// 1) Transpose + downconvert: ref (C,H,W) fp32 -> refT (H*W, C) fp16.
//    64-px tiles (16.6 KB smem) -> full occupancy for DRAM latency hiding.
// ---------------------------------------------------------------------------
__global__ __launch_bounds__(256) void transpose_ref_kernel(const float* __restrict__ ref) {
    __shared__ float tile[64][65];
    const int pixBase = blockIdx.x * 64;
    const int tid = threadIdx.x;

    #pragma unroll
    for (int it = 0; it < 4; it++) {
        const int i = tid + it * 256;
        const int c  = i >> 4;            // 0..63 channel
        const int p4 = i & 15;            // float4 within 64-px row
        const float4 v = __ldg((const float4*)(ref + (size_t)c * NPIX + pixBase + p4 * 4));
        tile[c][p4 * 4 + 0] = v.x; tile[c][p4 * 4 + 1] = v.y;
        tile[c][p4 * 4 + 2] = v.z; tile[c][p4 * 4 + 3] = v.w;
    }
    __syncthreads();

    #pragma unroll
    for (int it = 0; it < 2; it++) {
        const int idx = tid + it * 256;
        const int px = idx >> 3;          // 0..63
        const int chunk = idx & 7;        // 8 halves per chunk
        const int c0 = chunk * 8;
        uint4 o;
        __half2 h;
        h = __float22half2_rn(make_float2(tile[c0 + 0][px], tile[c0 + 1][px]));
        o.x = *(unsigned*)&h;
        h = __float22half2_rn(make_float2(tile[c0 + 2][px], tile[c0 + 3][px]));
        o.y = *(unsigned*)&h;
        h = __float22half2_rn(make_float2(tile[c0 + 4][px], tile[c0 + 5][px]));
        o.z = *(unsigned*)&h;
        h = __float22half2_rn(make_float2(tile[c0 + 6][px], tile[c0 + 7][px]));
        o.w = *(unsigned*)&h;
        ((uint4*)(g_refT + (size_t)(pixBase + px) * NC))[chunk] = o;
    }
}

// ---------------------------------------------------------------------------
// 2) Invert nnf_rs into buckets (one pixel/thread — the R11-proven version).
//    g_cnt is all-zero on entry (invariant).
// ---------------------------------------------------------------------------
__global__ __launch_bounds__(256) void build_buckets_kernel(const int* __restrict__ nnf_rs) {
    const int r = blockIdx.x * 256 + threadIdx.x;
    const int2 nn = __ldg(&((const int2*)nnf_rs)[r]);   // (sy, sx) in [0,512)
    const int key = nn.x * HW + nn.y;
    const int slot = atomicAdd(&g_cnt[key], 1);
    if (slot < CAP) g_bucket[slot][key] = r;
}

// ---------------------------------------------------------------------------
// 3) Precompute lists: one thread per pixel, NO smem. Slot-major g_list makes
//    every list store coalesced. Pass1 -> slots [0,m1), pass2 -> [9, 9+n2).
// ---------------------------------------------------------------------------
__global__ __launch_bounds__(256) void precompute_kernel(const int* __restrict__ nnf_sr) {
    const int t = blockIdx.x * 256 + threadIdx.x;
    const int ty = t >> 9;
    const int tx = t & (HW - 1);

    int m1 = 0;            // pass1 fill [0, m1), m1 <= 9
    int p2 = P2OFF;        // pass2 fill [9, p2)

    #pragma unroll
    for (int dy = -1; dy <= 1; dy++) {
        #pragma unroll
        for (int dx = -1; dx <= 1; dx++) {
            const int sy = ty - dy, sx = tx - dx;
            if ((unsigned)sy < HW && (unsigned)sx < HW) {
                const int sidx = sy * HW + sx;

                // pass 1: s -> nnf_sr[s]+d
                const int2 nn = __ldg(&((const int2*)nnf_sr)[sidx]);
                const int qy = nn.x + dy, qx = nn.y + dx;
                if ((unsigned)qy < HW && (unsigned)qx < HW)
                    g_list[m1++][t] = (qy * HW + qx) << 7;   // coalesced store

                // pass 2: bucket entries r with nnf_rs[r] = s, q = r+d
                int n = g_cnt[sidx];
                if (n > CAP) n = CAP;
                for (int i = 0; i < n; i++) {
                    const int r = g_bucket[i][sidx];          // coalesced (interleaved)
                    const int q2y = (r >> 9) + dy, q2x = (r & (HW - 1)) + dx;
                    if (((unsigned)q2y < HW) & ((unsigned)q2x < HW) && p2 < MAXS)
                        g_list[p2++][t] = ((q2y * HW + q2x) << 7);
                }
            }
        }
    }
    g_counts[t] = m1 | ((p2 - P2OFF) << 16);
}

// ---------------------------------------------------------------------------
// 4) Vote: FOUR pixels per warp, LDG.128 row gathers, SEL-masked padding,
//    fp16 PAIRWISE PRE-ADD (HADD2) before f32 conversion -> ~30% fewer
//    hot-loop instructions. Epilogue re-zeroes g_cnt (invariant).
// ---------------------------------------------------------------------------
__global__ __launch_bounds__(512) void vote_kernel(float* __restrict__ out) {
    __shared__ __align__(16) int s_list[MAXS * 64];   // [slot][px], 11 KB
    __shared__ float s_out[64][65];
    const int tid  = threadIdx.x;
    const int warp = tid >> 5;                    // 0..15
    const int lane = tid & 31;
    const int pixBase = blockIdx.x * 64;

    // Stage 44 slot-rows of 64 ints each (16 int4 per row), coalesced.
    #pragma unroll
    for (int i = tid; i < MAXS * 16; i += 512) {
        const int j = i >> 4;                     // slot row
        const int k = i & 15;                     // int4 within row
        ((int4*)s_list)[i] = __ldg(((const int4*)(&g_list[j][pixBase])) + k);
    }
    __syncthreads();

    const int group = lane >> 3;                  // 0..3 -> pixel within warp
    const int sub   = lane & 7;                   // 16-byte chunk within row
    const int px    = warp * 4 + group;           // 0..63
    const int t     = pixBase + px;

    const int packed = __ldg(&g_counts[t]);
    const int m1 = packed & 0xffff;
    const int n2 = packed >> 16;
    // warp max of n2 across the 4 groups
    int n2max = n2;
    n2max = max(n2max, __shfl_xor_sync(0xffffffffu, n2max, 8));
    n2max = max(n2max, __shfl_xor_sync(0xffffffffu, n2max, 16));

    // Invariant maintenance: g_cnt dead after setup; re-zero for next replay.
    if (tid < 64) g_cnt[pixBase + tid] = 0;

    const char* base = (const char*)g_refT + sub * 16;
    const int* col = s_list + px;                 // entry j at col[j * 64]

    unsigned long long a1[4] = {0ull, 0ull, 0ull, 0ull};
    unsigned long long a2[4] = {0ull, 0ull, 0ull, 0ull};

    #define H2(u) (*(const __half2*)&(u))
    #define ACC1(acc, h)                                                      \
    {                                                                         \
        const __half2 h_ = (h);                                               \
        const float2 v_ = __half22float2(h_);                                 \
        unsigned long long pv_;                                               \
        asm("mov.b64 %0, {%1, %2};" : "=l"(pv_) : "f"(v_.x), "f"(v_.y));      \
        asm("add.rn.f32x2 %0, %0, %1;" : "+l"(acc) : "l"(pv_));               \
    }
    // Pair of rows: pre-add in fp16 (4 HADD2), single convert chain.
    #define ACCP(acc, da, db) {                                               \
        ACC1(acc[0], __hadd2(H2((da).x), H2((db).x)));                        \
        ACC1(acc[1], __hadd2(H2((da).y), H2((db).y)));                        \
        ACC1(acc[2], __hadd2(H2((da).z), H2((db).z)));                        \
        ACC1(acc[3], __hadd2(H2((da).w), H2((db).w))); }
    #define ACC8(acc, d) { ACC1(acc[0], H2((d).x)); ACC1(acc[1], H2((d).y));  \
                           ACC1(acc[2], H2((d).z)); ACC1(acc[3], H2((d).w)); }

    // --- pass 1: fixed 9 slots, SEL-masked by m1: 4+4 paired, 1 single ---
    {
        const int o0 = (0 < m1) ? col[0 * 64] : (int)ZOFF;
        const int o1 = (1 < m1) ? col[1 * 64] : (int)ZOFF;
        const int o2 = (2 < m1) ? col[2 * 64] : (int)ZOFF;
        const int o3 = (3 < m1) ? col[3 * 64] : (int)ZOFF;
        const uint4 d0 = __ldg((const uint4*)(base + o0));
        const uint4 d1 = __ldg((const uint4*)(base + o1));
        const uint4 d2 = __ldg((const uint4*)(base + o2));
        const uint4 d3 = __ldg((const uint4*)(base + o3));
        ACCP(a1, d0, d1); ACCP(a1, d2, d3);
    }
    {
        const int o4 = (4 < m1) ? col[4 * 64] : (int)ZOFF;
        const int o5 = (5 < m1) ? col[5 * 64] : (int)ZOFF;
        const int o6 = (6 < m1) ? col[6 * 64] : (int)ZOFF;
        const int o7 = (7 < m1) ? col[7 * 64] : (int)ZOFF;
        const uint4 d4 = __ldg((const uint4*)(base + o4));
        const uint4 d5 = __ldg((const uint4*)(base + o5));
        const uint4 d6 = __ldg((const uint4*)(base + o6));
        const uint4 d7 = __ldg((const uint4*)(base + o7));
        ACCP(a1, d4, d5); ACCP(a1, d6, d7);
        const int o8 = (8 < m1) ? col[8 * 64] : (int)ZOFF;
        const uint4 d8 = __ldg((const uint4*)(base + o8));
        ACC8(a1, d8);
    }

    // --- pass 2: dynamic to warp-max, SEL-masked by n2, paired chunks of 2 ---
    for (int j = 0; j < n2max; j += 2) {
        const int o0 = (j     < n2) ? col[(P2OFF + j    ) * 64] : (int)ZOFF;
        const int o1 = (j + 1 < n2) ? col[(P2OFF + j + 1) * 64] : (int)ZOFF;
        const uint4 d0 = __ldg((const uint4*)(base + o0));
        const uint4 d1 = __ldg((const uint4*)(base + o1));
        ACCP(a2, d0, d1);
    }
    #undef ACC8
    #undef ACCP
    #undef ACC1
    #undef H2

    const float ws = 1.0f / (float)NPIX;
    const float wr = 2.0f / (float)NPIX;
    const float w  = ws * (float)m1 + wr * (float)n2;
    const float inv = (w == 0.f) ? 1.f : (1.f / w);

    #pragma unroll
    for (int k = 0; k < 4; k++) {
        float2 v1, v2;
        asm("mov.b64 {%0, %1}, %2;" : "=f"(v1.x), "=f"(v1.y) : "l"(a1[k]));
        asm("mov.b64 {%0, %1}, %2;" : "=f"(v2.x), "=f"(v2.y) : "l"(a2[k]));
        s_out[px][sub * 8 + 2 * k]     = (ws * v1.x + wr * v2.x) * inv;
        s_out[px][sub * 8 + 2 * k + 1] = (ws * v1.y + wr * v2.y) * inv;
    }
    __syncthreads();

    // Writeout: 64 px x 64 ch = 4096 floats, coalesced 64-float rows.
    #pragma unroll
    for (int i = tid; i < 4096; i += 512) {
        const int c = i >> 6;
        const int p = i & 63;
        out[(size_t)c * NPIX + pixBase + p] = s_out[p][c];
    }
}

// ---------------------------------------------------------------------------
extern "C" void kernel_launch(void* const* d_in, const int* in_sizes, int n_in,
                              void* d_out, int out_size) {
    const float* ref    = (const float*)d_in[0];
    const int*   nnf_sr = (const int*)d_in[1];
    const int*   nnf_rs = (const int*)d_in[2];
    float*       out    = (float*)d_out;

    transpose_ref_kernel<<<NPIX / 64, 256>>>(ref);
    build_buckets_kernel<<<NPIX / 256, 256>>>(nnf_rs);
    precompute_kernel<<<NPIX / 256, 256>>>(nnf_sr);
    vote_kernel<<<NPIX / 64, 512>>>(out);
}